// round 3
// baseline (speedup 1.0000x reference)
#include <cuda_runtime.h>
#include <math.h>

typedef unsigned long long u64;

#define S_SPLIT 32
#define KC      128

// scratch (device globals; no allocs allowed)
__device__ float g_qkv_part[S_SPLIT * 32 * 6144];
__device__ float g_qkv[32 * 6144];
__device__ float g_attn[32 * 4096];
__device__ float g_wo_part[S_SPLIT * 32 * 4096];

__device__ __forceinline__ u64 f2pack(float lo, float hi) {
    u64 r; asm("mov.b64 %0,{%1,%2};" : "=l"(r) : "f"(lo), "f"(hi)); return r;
}
__device__ __forceinline__ u64 ffma2(u64 a, u64 b, u64 c) {
    u64 d; asm("fma.rn.f32x2 %0,%1,%2,%3;" : "=l"(d) : "l"(a), "l"(b), "l"(c)); return d;
}
__device__ __forceinline__ float f2lo(u64 v) {
    float lo, hi; asm("mov.b64 {%0,%1},%2;" : "=f"(lo), "=f"(hi) : "l"(v)); return lo;
}
__device__ __forceinline__ float f2hi(u64 v) {
    float lo, hi; asm("mov.b64 {%0,%1},%2;" : "=f"(lo), "=f"(hi) : "l"(v)); return hi;
}

// ---- split-K GEMM partial: part[s][m][c] = sum_{k in split} A[m][k]*W[k][c]
__global__ __launch_bounds__(128, 2)
void gemm_split(const float* __restrict__ A, const float* __restrict__ W,
                float* __restrict__ part, int N)
{
    __shared__ float2 as2[32][KC];
    const int K = 4096;
    const int k0 = blockIdx.y * KC;
    const int c0 = blockIdx.x * 512 + threadIdx.x * 4;

    for (int i = threadIdx.x; i < 32 * KC; i += 128) {
        int m = i >> 7, kk = i & (KC - 1);
        float a = A[m * K + k0 + kk];
        as2[m][kk] = make_float2(a, a);
    }
    __syncthreads();

    u64 acc01[32], acc23[32];
#pragma unroll
    for (int m = 0; m < 32; m++) { acc01[m] = 0ull; acc23[m] = 0ull; }

    const float* Wp = W + (size_t)k0 * N + c0;
#pragma unroll 2
    for (int kk = 0; kk < KC; kk++) {
        u64 w01 = *(const u64*)(Wp);
        u64 w23 = *(const u64*)(Wp + 2);
        Wp += N;
#pragma unroll
        for (int m = 0; m < 32; m++) {
            u64 a2 = *(const u64*)&as2[m][kk];
            acc01[m] = ffma2(a2, w01, acc01[m]);
            acc23[m] = ffma2(a2, w23, acc23[m]);
        }
    }

    float* op = part + (size_t)blockIdx.y * 32 * N + c0;
#pragma unroll
    for (int m = 0; m < 32; m++) {
        *(u64*)(op + (size_t)m * N)     = acc01[m];
        *(u64*)(op + (size_t)m * N + 2) = acc23[m];
    }
}

// ---- reduce QKV partials + RoPE (q,k). One block per batch row.
__global__ void qkv_reduce_rope(const int* __restrict__ pos1d)
{
    __shared__ float cs[64], sn[64];
    const int b = blockIdx.x;
    const int tid = threadIdx.x;

    if (tid < 64) {
        float freq = (float)pow(1.0e6, -(double)tid / 64.0); // match f32 inv_freq
        float ang = (float)pos1d[b] * freq;
        double sd, cd; sincos((double)ang, &sd, &cd);
        cs[tid] = (float)cd; sn[tid] = (float)sd;
    }
    __syncthreads();

    for (int idx = tid; idx < 3584; idx += blockDim.x) {
        if (idx < 2560) {
            int col1, j;
            if (idx < 2048) { int h = idx >> 6; j = idx & 63; col1 = h * 128 + j; }
            else { int t = idx - 2048; int kvh = t >> 6; j = t & 63; col1 = 4096 + kvh * 128 + j; }
            int col2 = col1 + 64;
            float x1 = 0.f, x2 = 0.f;
#pragma unroll
            for (int s = 0; s < S_SPLIT; s++) {
                x1 += g_qkv_part[(s * 32 + b) * 6144 + col1];
                x2 += g_qkv_part[(s * 32 + b) * 6144 + col2];
            }
            float c = cs[j], sv = sn[j];
            g_qkv[b * 6144 + col1] = x1 * c - x2 * sv;
            g_qkv[b * 6144 + col2] = x2 * c + x1 * sv;
        } else {
            int col = 5120 + (idx - 2560);
            float x = 0.f;
#pragma unroll
            for (int s = 0; s < S_SPLIT; s++)
                x += g_qkv_part[(s * 32 + b) * 6144 + col];
            g_qkv[b * 6144 + col] = x;
        }
    }
}

__device__ __forceinline__ float4 warpRedMax4(float4 v) {
#pragma unroll
    for (int o = 16; o > 0; o >>= 1) {
        v.x = fmaxf(v.x, __shfl_xor_sync(0xffffffffu, v.x, o));
        v.y = fmaxf(v.y, __shfl_xor_sync(0xffffffffu, v.y, o));
        v.z = fmaxf(v.z, __shfl_xor_sync(0xffffffffu, v.z, o));
        v.w = fmaxf(v.w, __shfl_xor_sync(0xffffffffu, v.w, o));
    }
    return v;
}
__device__ __forceinline__ float4 warpRedSum4(float4 v) {
#pragma unroll
    for (int o = 16; o > 0; o >>= 1) {
        v.x += __shfl_xor_sync(0xffffffffu, v.x, o);
        v.y += __shfl_xor_sync(0xffffffffu, v.y, o);
        v.z += __shfl_xor_sync(0xffffffffu, v.z, o);
        v.w += __shfl_xor_sync(0xffffffffu, v.w, o);
    }
    return v;
}
__device__ float4 blockRedMax4(float4 v, float4* red) {
    v = warpRedMax4(v);
    int w = threadIdx.x >> 5, lane = threadIdx.x & 31;
    if (lane == 0) red[w] = v;
    __syncthreads();
    if (w == 0) {
        float4 t = (lane < 8) ? red[lane] : make_float4(-1e30f, -1e30f, -1e30f, -1e30f);
        t = warpRedMax4(t);
        if (lane == 0) red[0] = t;
    }
    __syncthreads();
    return red[0];
}
__device__ float4 blockRedSum4(float4 v, float4* red) {
    v = warpRedSum4(v);
    int w = threadIdx.x >> 5, lane = threadIdx.x & 31;
    if (lane == 0) red[w] = v;
    __syncthreads();
    if (w == 0) {
        float4 t = (lane < 8) ? red[lane] : make_float4(0.f, 0.f, 0.f, 0.f);
        t = warpRedSum4(t);
        if (lane == 0) red[0] = t;
    }
    __syncthreads();
    return red[0];
}

// ---- paged GQA attention: 1 block per (b, kv_head); 4 q-heads, 4096 keys
#define ATTN_SMEM (65536 + 2048 + 1024)

__global__ __launch_bounds__(256)
void attn_kernel(const float* __restrict__ kc, const float* __restrict__ vc,
                 const int* __restrict__ blkoff, const int* __restrict__ kvlens)
{
    extern __shared__ float sm[];
    float* sc = sm;                  // s[l][g], 16384 floats
    float* qp = sm + 16384;          // q[d][g]*scale, 512 floats
    float4* red = (float4*)(sm + 16896);
    __shared__ int pblk[64];

    const int b = blockIdx.x >> 3, kvh = blockIdx.x & 7;
    const int tid = threadIdx.x;
    const int Lv = kvlens[b];
    const int posn = Lv - 1;
    const float* qkv_b = g_qkv + b * 6144;

    for (int i = tid; i < 512; i += 256) {
        int d = i >> 2, g = i & 3;
        qp[i] = qkv_b[(kvh * 4 + g) * 128 + d] * 0.08838834764831845f;
    }
    if (tid < 64) pblk[tid] = blkoff[b * 64 + tid];
    __syncthreads();

    const float4* qp4 = (const float4*)qp;

    // Phase 1: scores
    float4 mx = make_float4(-1e30f, -1e30f, -1e30f, -1e30f);
#pragma unroll 1
    for (int i = 0; i < 16; i++) {
        int l = tid + (i << 8);
        float4 sv = make_float4(-1e30f, -1e30f, -1e30f, -1e30f);
        if (l < Lv) {
            const float* krow;
            if (l == posn) krow = qkv_b + 4096 + kvh * 128;
            else {
                int phys = pblk[l >> 6];
                krow = kc + (((size_t)phys * 64 + (l & 63)) * 8 + kvh) * 128;
            }
            const float4* k4 = (const float4*)krow;
            float a0 = 0.f, a1 = 0.f, a2 = 0.f, a3 = 0.f;
#pragma unroll 8
            for (int d4 = 0; d4 < 32; d4++) {
                float4 kv = k4[d4];
                float4 qa = qp4[d4 * 4 + 0];
                a0 += kv.x * qa.x; a1 += kv.x * qa.y; a2 += kv.x * qa.z; a3 += kv.x * qa.w;
                float4 qb = qp4[d4 * 4 + 1];
                a0 += kv.y * qb.x; a1 += kv.y * qb.y; a2 += kv.y * qb.z; a3 += kv.y * qb.w;
                float4 qc = qp4[d4 * 4 + 2];
                a0 += kv.z * qc.x; a1 += kv.z * qc.y; a2 += kv.z * qc.z; a3 += kv.z * qc.w;
                float4 qd = qp4[d4 * 4 + 3];
                a0 += kv.w * qd.x; a1 += kv.w * qd.y; a2 += kv.w * qd.z; a3 += kv.w * qd.w;
            }
            sv = make_float4(a0, a1, a2, a3);
            mx.x = fmaxf(mx.x, a0); mx.y = fmaxf(mx.y, a1);
            mx.z = fmaxf(mx.z, a2); mx.w = fmaxf(mx.w, a3);
        }
        ((float4*)sc)[l] = sv;
    }
    __syncthreads();
    mx = blockRedMax4(mx, red);

    // Phase 2: exp + sum
    float4 sum = make_float4(0.f, 0.f, 0.f, 0.f);
#pragma unroll 1
    for (int i = 0; i < 16; i++) {
        int l = tid + (i << 8);
        float4 sv = ((float4*)sc)[l];
        sv.x = __expf(sv.x - mx.x); sv.y = __expf(sv.y - mx.y);
        sv.z = __expf(sv.z - mx.z); sv.w = __expf(sv.w - mx.w);
        sum.x += sv.x; sum.y += sv.y; sum.z += sv.z; sum.w += sv.w;
        ((float4*)sc)[l] = sv;
    }
    __syncthreads();
    sum = blockRedSum4(sum, red);
    float4 inv = make_float4(1.f / sum.x, 1.f / sum.y, 1.f / sum.z, 1.f / sum.w);
    __syncthreads();

    // Phase 3: PV. thread = (d-pair, g-pair, l-half)
    const int d2 = tid & 63;
    const int gp = (tid >> 6) & 1;
    const int rep = tid >> 7;
    const u64* scu = (const u64*)sc;
    u64 accA = 0ull, accB = 0ull;
    const int lbeg = rep * 2048;
#pragma unroll 4
    for (int l = lbeg; l < lbeg + 2048; l++) {
        if (l >= Lv) break;
        const float* vrow;
        if (l == posn) vrow = qkv_b + 5120 + kvh * 128;
        else {
            int phys = pblk[l >> 6];
            vrow = vc + (((size_t)phys * 64 + (l & 63)) * 8 + kvh) * 128;
        }
        float2 v2 = *(const float2*)(vrow + d2 * 2);
        u64 p2 = scu[l * 2 + gp];
        accA = ffma2(f2pack(v2.x, v2.x), p2, accA);
        accB = ffma2(f2pack(v2.y, v2.y), p2, accB);
    }
    __syncthreads();
    float4* comb = (float4*)sc;
    comb[tid] = make_float4(f2lo(accA), f2hi(accA), f2lo(accB), f2hi(accB));
    __syncthreads();
    if (rep == 0) {
        float4 o = comb[tid], p = comb[tid + 128];
        o.x += p.x; o.y += p.y; o.z += p.z; o.w += p.w;
        int g0 = gp * 2, g1 = g0 + 1;
        float i0 = (gp == 0) ? inv.x : inv.z;
        float i1 = (gp == 0) ? inv.y : inv.w;
        int d0 = d2 * 2, d1 = d0 + 1;
        float* ob = g_attn + b * 4096 + (kvh * 4) * 128;
        ob[g0 * 128 + d0] = o.x * i0;
        ob[g1 * 128 + d0] = o.y * i1;
        ob[g0 * 128 + d1] = o.z * i0;
        ob[g1 * 128 + d1] = o.w * i1;
    }
}

// ---- final split-K reduction into d_out
__global__ void reduce_out(float* __restrict__ out, int n)
{
    int i = blockIdx.x * blockDim.x + threadIdx.x;
    if (i < n) {
        float x = 0.f;
#pragma unroll
        for (int s = 0; s < S_SPLIT; s++) x += g_wo_part[(size_t)s * n + i];
        out[i] = x;
    }
}

extern "C" void kernel_launch(void* const* d_in, const int* in_sizes, int n_in,
                              void* d_out, int out_size)
{
    const float* hidden = (const float*)d_in[0];
    const float* wqkv   = (const float*)d_in[1];
    const float* wo     = (const float*)d_in[2];
    const float* kc     = (const float*)d_in[3];
    const float* vc     = (const float*)d_in[4];
    const int*   pos1d  = (const int*)d_in[5];
    const int*   blkoff = (const int*)d_in[6];
    const int*   kvlens = (const int*)d_in[7];
    float* out = (float*)d_out;

    static bool attr_done = false;
    if (!attr_done) {
        cudaFuncSetAttribute(attn_kernel, cudaFuncAttributeMaxDynamicSharedMemorySize, ATTN_SMEM);
        attr_done = true;
    }

    float *qkv_part, *wo_part, *attn_in;
    cudaGetSymbolAddress((void**)&qkv_part, g_qkv_part);
    cudaGetSymbolAddress((void**)&wo_part,  g_wo_part);
    cudaGetSymbolAddress((void**)&attn_in,  g_attn);

    // 1) QKV GEMM partials: N=6144, grid (12 col-blocks, 32 k-splits)
    gemm_split<<<dim3(12, 32), 128>>>(hidden, wqkv, qkv_part, 6144);
    // 2) reduce + RoPE
    qkv_reduce_rope<<<32, 256>>>(pos1d);
    // 3) attention: 256 blocks of 256 threads
    attn_kernel<<<256, 256, ATTN_SMEM>>>(kc, vc, blkoff, kvlens);
    // 4) WO GEMM partials: N=4096, grid (8, 32)
    gemm_split<<<dim3(8, 32), 128>>>(attn_in, wo, wo_part, 4096);
    // 5) final reduction: 32*4096 outputs
    reduce_out<<<512, 256>>>(out, 32 * 4096);
}

// round 4
// speedup vs baseline: 1.6784x; 1.6784x over previous
#include <cuda_runtime.h>
#include <math.h>

typedef unsigned long long u64;

#define S_SPLIT 32
#define KC      128

__device__ float g_qkv_part[S_SPLIT * 32 * 6144];
__device__ float g_qkv[32 * 6144];
__device__ float g_attn[32 * 4096];
__device__ float g_wo_part[S_SPLIT * 32 * 4096];

__device__ __forceinline__ u64 f2pack(float lo, float hi) {
    u64 r; asm("mov.b64 %0,{%1,%2};" : "=l"(r) : "f"(lo), "f"(hi)); return r;
}
__device__ __forceinline__ u64 ffma2(u64 a, u64 b, u64 c) {
    u64 d; asm("fma.rn.f32x2 %0,%1,%2,%3;" : "=l"(d) : "l"(a), "l"(b), "l"(c)); return d;
}
__device__ __forceinline__ float f2lo(u64 v) {
    float lo, hi; asm("mov.b64 {%0,%1},%2;" : "=f"(lo), "=f"(hi) : "l"(v)); return lo;
}
__device__ __forceinline__ float f2hi(u64 v) {
    float lo, hi; asm("mov.b64 {%0,%1},%2;" : "=f"(lo), "=f"(hi) : "l"(v)); return hi;
}

// ---- split-K GEMM partial: part[s][m][c] = sum_{k in split} A[m][k]*W[k][c]
__global__ __launch_bounds__(128, 2)
void gemm_split(const float* __restrict__ A, const float* __restrict__ W,
                float* __restrict__ part, int N)
{
    __shared__ float2 as2[32][KC];
    const int K = 4096;
    const int k0 = blockIdx.y * KC;
    const int c0 = blockIdx.x * 512 + threadIdx.x * 4;

    for (int i = threadIdx.x; i < 32 * KC; i += 128) {
        int m = i >> 7, kk = i & (KC - 1);
        float a = A[m * K + k0 + kk];
        as2[m][kk] = make_float2(a, a);
    }
    __syncthreads();

    u64 acc01[32], acc23[32];
#pragma unroll
    for (int m = 0; m < 32; m++) { acc01[m] = 0ull; acc23[m] = 0ull; }

    const float* Wp = W + (size_t)k0 * N + c0;
#pragma unroll 1
    for (int kk = 0; kk < KC; kk += 2) {
        u64 w01a = *(const u64*)(Wp);
        u64 w23a = *(const u64*)(Wp + 2);
        u64 w01b = *(const u64*)(Wp + N);
        u64 w23b = *(const u64*)(Wp + N + 2);
        Wp += 2 * N;
#pragma unroll
        for (int m = 0; m < 32; m++) {
            const u64* pa = (const u64*)&as2[m][kk];   // 16B aligned (kk even)
            u64 a0 = pa[0], a1 = pa[1];
            acc01[m] = ffma2(a0, w01a, acc01[m]);
            acc23[m] = ffma2(a0, w23a, acc23[m]);
            acc01[m] = ffma2(a1, w01b, acc01[m]);
            acc23[m] = ffma2(a1, w23b, acc23[m]);
        }
    }

    float* op = part + (size_t)blockIdx.y * 32 * N + c0;
#pragma unroll
    for (int m = 0; m < 32; m++) {
        *(u64*)(op + (size_t)m * N)     = acc01[m];
        *(u64*)(op + (size_t)m * N + 2) = acc23[m];
    }
}

// ---- reduce QKV partials + RoPE (q,k). One block per batch row.
__global__ void qkv_reduce_rope(const int* __restrict__ pos1d)
{
    __shared__ float cs[64], sn[64];
    const int b = blockIdx.x;
    const int tid = threadIdx.x;

    if (tid < 64) {
        float freq = (float)pow(1.0e6, -(double)tid / 64.0);
        float ang = (float)pos1d[b] * freq;
        double sd, cd; sincos((double)ang, &sd, &cd);
        cs[tid] = (float)cd; sn[tid] = (float)sd;
    }
    __syncthreads();

    for (int idx = tid; idx < 3584; idx += blockDim.x) {
        if (idx < 2560) {
            int col1, j;
            if (idx < 2048) { int h = idx >> 6; j = idx & 63; col1 = h * 128 + j; }
            else { int t = idx - 2048; int kvh = t >> 6; j = t & 63; col1 = 4096 + kvh * 128 + j; }
            int col2 = col1 + 64;
            float x1 = 0.f, x2 = 0.f;
#pragma unroll
            for (int s = 0; s < S_SPLIT; s++) {
                x1 += g_qkv_part[(s * 32 + b) * 6144 + col1];
                x2 += g_qkv_part[(s * 32 + b) * 6144 + col2];
            }
            float c = cs[j], sv = sn[j];
            g_qkv[b * 6144 + col1] = x1 * c - x2 * sv;
            g_qkv[b * 6144 + col2] = x2 * c + x1 * sv;
        } else {
            int col = 5120 + (idx - 2560);
            float x = 0.f;
#pragma unroll
            for (int s = 0; s < S_SPLIT; s++)
                x += g_qkv_part[(s * 32 + b) * 6144 + col];
            g_qkv[b * 6144 + col] = x;
        }
    }
}

__device__ __forceinline__ float4 warpRedMax4(float4 v) {
#pragma unroll
    for (int o = 16; o > 0; o >>= 1) {
        v.x = fmaxf(v.x, __shfl_xor_sync(0xffffffffu, v.x, o));
        v.y = fmaxf(v.y, __shfl_xor_sync(0xffffffffu, v.y, o));
        v.z = fmaxf(v.z, __shfl_xor_sync(0xffffffffu, v.z, o));
        v.w = fmaxf(v.w, __shfl_xor_sync(0xffffffffu, v.w, o));
    }
    return v;
}
__device__ __forceinline__ float4 warpRedSum4(float4 v) {
#pragma unroll
    for (int o = 16; o > 0; o >>= 1) {
        v.x += __shfl_xor_sync(0xffffffffu, v.x, o);
        v.y += __shfl_xor_sync(0xffffffffu, v.y, o);
        v.z += __shfl_xor_sync(0xffffffffu, v.z, o);
        v.w += __shfl_xor_sync(0xffffffffu, v.w, o);
    }
    return v;
}
__device__ float4 blockRedMax4(float4 v, float4* red) {
    v = warpRedMax4(v);
    int w = threadIdx.x >> 5, lane = threadIdx.x & 31;
    if (lane == 0) red[w] = v;
    __syncthreads();
    if (w == 0) {
        float4 t = (lane < 8) ? red[lane] : make_float4(-1e30f, -1e30f, -1e30f, -1e30f);
        t = warpRedMax4(t);
        if (lane == 0) red[0] = t;
    }
    __syncthreads();
    return red[0];
}
__device__ float4 blockRedSum4(float4 v, float4* red) {
    v = warpRedSum4(v);
    int w = threadIdx.x >> 5, lane = threadIdx.x & 31;
    if (lane == 0) red[w] = v;
    __syncthreads();
    if (w == 0) {
        float4 t = (lane < 8) ? red[lane] : make_float4(0.f, 0.f, 0.f, 0.f);
        t = warpRedSum4(t);
        if (lane == 0) red[0] = t;
    }
    __syncthreads();
    return red[0];
}

// ---- paged GQA attention: 1 block per (b, kv_head); 4 q-heads, 4096 keys
#define ATTN_SMEM ((16384 + 512) * 4 + 128)

__global__ __launch_bounds__(256)
void attn_kernel(const float* __restrict__ kc, const float* __restrict__ vc,
                 const int* __restrict__ blkoff, const int* __restrict__ kvlens)
{
    extern __shared__ float sm[];
    float* sc = sm;                  // s[l][g], 16384 floats
    float* qp = sm + 16384;          // q[g][d]*scale, 512 floats
    float4* red = (float4*)(sm + 16896);
    __shared__ int pblk[64];

    const int b = blockIdx.x >> 3, kvh = blockIdx.x & 7;
    const int tid = threadIdx.x;
    const int Lv = kvlens[b];
    const int posn = Lv - 1;
    const float* qkv_b = g_qkv + b * 6144;

    for (int i = tid; i < 512; i += 256) {
        int g = i >> 7, d = i & 127;
        qp[i] = qkv_b[(kvh * 4 + g) * 128 + d] * 0.08838834764831845f;
    }
    if (tid < 64) pblk[tid] = blkoff[b * 64 + tid];
    __syncthreads();

    // ---- Phase 1: QK. Warp = 4 rows x 8 lanes; each lane covers 16 dims.
    const int lane8  = tid & 7;     // d-chunk within row
    const int rowoff = tid >> 3;    // 0..31: row within pass

    float4 qr[4][4];                // q[g][lane8*16 + i*4 .. +3], in registers
#pragma unroll
    for (int g = 0; g < 4; g++)
#pragma unroll
        for (int i = 0; i < 4; i++)
            qr[g][i] = *(const float4*)&qp[g * 128 + lane8 * 16 + i * 4];

    float4 mx = make_float4(-1e30f, -1e30f, -1e30f, -1e30f);
#pragma unroll 2
    for (int pass = 0; pass < 128; pass++) {
        int l = pass * 32 + rowoff;
        const float* krow;
        if (l == posn) krow = qkv_b + 4096 + kvh * 128;
        else {
            int phys = pblk[l >> 6];
            krow = kc + (((size_t)phys * 64 + (l & 63)) * 8 + kvh) * 128;
        }
        const float4* k4 = (const float4*)(krow) + lane8 * 4;
        float4 k0 = k4[0], k1 = k4[1], k2 = k4[2], k3 = k4[3];
        float a0 = 0.f, a1 = 0.f, a2 = 0.f, a3 = 0.f;
#define DOTG(kk, qq, acc) acc += kk.x*qq.x + kk.y*qq.y + kk.z*qq.z + kk.w*qq.w
        DOTG(k0, qr[0][0], a0); DOTG(k1, qr[0][1], a0); DOTG(k2, qr[0][2], a0); DOTG(k3, qr[0][3], a0);
        DOTG(k0, qr[1][0], a1); DOTG(k1, qr[1][1], a1); DOTG(k2, qr[1][2], a1); DOTG(k3, qr[1][3], a1);
        DOTG(k0, qr[2][0], a2); DOTG(k1, qr[2][1], a2); DOTG(k2, qr[2][2], a2); DOTG(k3, qr[2][3], a2);
        DOTG(k0, qr[3][0], a3); DOTG(k1, qr[3][1], a3); DOTG(k2, qr[3][2], a3); DOTG(k3, qr[3][3], a3);
#undef DOTG
#pragma unroll
        for (int o = 4; o > 0; o >>= 1) {
            a0 += __shfl_xor_sync(0xffffffffu, a0, o);
            a1 += __shfl_xor_sync(0xffffffffu, a1, o);
            a2 += __shfl_xor_sync(0xffffffffu, a2, o);
            a3 += __shfl_xor_sync(0xffffffffu, a3, o);
        }
        if (lane8 == 0) ((float4*)sc)[l] = make_float4(a0, a1, a2, a3);
        if (l < Lv) {
            mx.x = fmaxf(mx.x, a0); mx.y = fmaxf(mx.y, a1);
            mx.z = fmaxf(mx.z, a2); mx.w = fmaxf(mx.w, a3);
        }
    }
    __syncthreads();
    mx = blockRedMax4(mx, red);

    // ---- Phase 2: exp + sum (thread per l, float4 over g) ------------------
    float4 sum = make_float4(0.f, 0.f, 0.f, 0.f);
#pragma unroll 1
    for (int i = 0; i < 16; i++) {
        int l = tid + (i << 8);
        float4 sv = ((float4*)sc)[l];
        bool valid = (l < Lv);
        sv.x = valid ? __expf(sv.x - mx.x) : 0.f;
        sv.y = valid ? __expf(sv.y - mx.y) : 0.f;
        sv.z = valid ? __expf(sv.z - mx.z) : 0.f;
        sv.w = valid ? __expf(sv.w - mx.w) : 0.f;
        sum.x += sv.x; sum.y += sv.y; sum.z += sv.z; sum.w += sv.w;
        ((float4*)sc)[l] = sv;
    }
    __syncthreads();
    sum = blockRedSum4(sum, red);
    float4 inv = make_float4(1.f / sum.x, 1.f / sum.y, 1.f / sum.z, 1.f / sum.w);
    __syncthreads();

    // ---- Phase 3: PV. thread = (d-pair, g-pair, l-half); batched MLP=8 -----
    const int d2  = tid & 63;
    const int gp  = (tid >> 6) & 1;
    const int rep = tid >> 7;
    const u64* scu = (const u64*)sc;
    u64 accA = 0ull, accB = 0ull;
    const int lbeg = rep * 2048;
    const int lend = min(lbeg + 2048, posn);   // cache rows only; posn handled below

    int l = lbeg;
    for (; l + 8 <= lend; l += 8) {
        float2 v[8]; u64 p[8];
#pragma unroll
        for (int j = 0; j < 8; j++) {
            int ll = l + j;
            int phys = pblk[ll >> 6];
            v[j] = *(const float2*)(vc + (((size_t)phys * 64 + (ll & 63)) * 8 + kvh) * 128 + d2 * 2);
        }
#pragma unroll
        for (int j = 0; j < 8; j++) p[j] = scu[(l + j) * 2 + gp];
#pragma unroll
        for (int j = 0; j < 8; j++) {
            accA = ffma2(f2pack(v[j].x, v[j].x), p[j], accA);
            accB = ffma2(f2pack(v[j].y, v[j].y), p[j], accB);
        }
    }
    for (; l < lend; l++) {
        int phys = pblk[l >> 6];
        float2 v2 = *(const float2*)(vc + (((size_t)phys * 64 + (l & 63)) * 8 + kvh) * 128 + d2 * 2);
        u64 p2 = scu[l * 2 + gp];
        accA = ffma2(f2pack(v2.x, v2.x), p2, accA);
        accB = ffma2(f2pack(v2.y, v2.y), p2, accB);
    }
    if (posn >= lbeg && posn < lbeg + 2048) {   // fresh-token V row
        float2 v2 = *(const float2*)(qkv_b + 5120 + kvh * 128 + d2 * 2);
        u64 p2 = scu[posn * 2 + gp];
        accA = ffma2(f2pack(v2.x, v2.x), p2, accA);
        accB = ffma2(f2pack(v2.y, v2.y), p2, accB);
    }
    __syncthreads();
    float4* comb = (float4*)sc;
    comb[tid] = make_float4(f2lo(accA), f2hi(accA), f2lo(accB), f2hi(accB));
    __syncthreads();
    if (rep == 0) {
        float4 o = comb[tid], p = comb[tid + 128];
        o.x += p.x; o.y += p.y; o.z += p.z; o.w += p.w;
        int g0 = gp * 2, g1 = g0 + 1;
        float i0 = (gp == 0) ? inv.x : inv.z;
        float i1 = (gp == 0) ? inv.y : inv.w;
        int d0 = d2 * 2, d1 = d0 + 1;
        float* ob = g_attn + b * 4096 + (kvh * 4) * 128;
        ob[g0 * 128 + d0] = o.x * i0;
        ob[g1 * 128 + d0] = o.y * i1;
        ob[g0 * 128 + d1] = o.z * i0;
        ob[g1 * 128 + d1] = o.w * i1;
    }
}

// ---- final split-K reduction into d_out
__global__ void reduce_out(float* __restrict__ out, int n)
{
    int i = blockIdx.x * blockDim.x + threadIdx.x;
    if (i < n) {
        float x = 0.f;
#pragma unroll
        for (int s = 0; s < S_SPLIT; s++) x += g_wo_part[(size_t)s * n + i];
        out[i] = x;
    }
}

extern "C" void kernel_launch(void* const* d_in, const int* in_sizes, int n_in,
                              void* d_out, int out_size)
{
    const float* hidden = (const float*)d_in[0];
    const float* wqkv   = (const float*)d_in[1];
    const float* wo     = (const float*)d_in[2];
    const float* kc     = (const float*)d_in[3];
    const float* vc     = (const float*)d_in[4];
    const int*   pos1d  = (const int*)d_in[5];
    const int*   blkoff = (const int*)d_in[6];
    const int*   kvlens = (const int*)d_in[7];
    float* out = (float*)d_out;

    static bool attr_done = false;
    if (!attr_done) {
        cudaFuncSetAttribute(attn_kernel, cudaFuncAttributeMaxDynamicSharedMemorySize, ATTN_SMEM);
        attr_done = true;
    }

    float *qkv_part, *wo_part, *attn_in;
    cudaGetSymbolAddress((void**)&qkv_part, g_qkv_part);
    cudaGetSymbolAddress((void**)&wo_part,  g_wo_part);
    cudaGetSymbolAddress((void**)&attn_in,  g_attn);

    gemm_split<<<dim3(12, 32), 128>>>(hidden, wqkv, qkv_part, 6144);
    qkv_reduce_rope<<<32, 256>>>(pos1d);
    attn_kernel<<<256, 256, ATTN_SMEM>>>(kc, vc, blkoff, kvlens);
    gemm_split<<<dim3(8, 32), 128>>>(attn_in, wo, wo_part, 4096);
    reduce_out<<<512, 256>>>(out, 32 * 4096);
}